// round 7
// baseline (speedup 1.0000x reference)
#include <cuda_runtime.h>
#include <cuda_fp16.h>

#define N_NODES 4096
#define N_CHILD 16384
#define DEGREE  64
#define BATCH   128
#define NNZ     (N_NODES * DEGREE)
#define ROWB    224   // 14-bit packed row: 128B hi + 64B nib + 32B crumb

// Scratch: per child c, 128 batch values of exp(child_ll) packed to 14 bits
// (fp16 rounded to m8): row = [hi bytes(15:8)][nibbles(7:4)][crumbs(3:2)].
__device__ __align__(32) unsigned char g_E14[(size_t)N_CHILD * ROWB];  // 3.5 MB

// ---------------------------------------------------------------------------
// Kernel 1: exp + transpose + 14-bit pack.
// child_ll [B=128, C=16384] f32 row-major -> g_E14 [C] rows of 224B.
// ---------------------------------------------------------------------------
__global__ void __launch_bounds__(256) exp_tr_kernel(
    const float* __restrict__ child_ll) {
    __shared__ float tile[64][65];
    const int c0 = blockIdx.x * 64;
    const int b0 = blockIdx.y * 64;

    const int q  = threadIdx.x & 15;
    const int r0 = threadIdx.x >> 4;
#pragma unroll
    for (int rr = 0; rr < 64; rr += 16) {
        const int r = r0 + rr;
        const float4 v = __ldcg(reinterpret_cast<const float4*>(
            &child_ll[(size_t)(b0 + r) * N_CHILD + c0 + q * 4]));
        tile[q * 4 + 0][r] = v.x;
        tile[q * 4 + 1][r] = v.y;
        tile[q * 4 + 2][r] = v.z;
        tile[q * 4 + 3][r] = v.w;
    }
    __syncthreads();

    const int c = threadIdx.x >> 2;    // 0..63
    const int s = threadIdx.x & 3;     // 0..3
    unsigned char* row = g_E14 + (size_t)(c0 + c) * ROWB;
#pragma unroll
    for (int h = 0; h < 2; h++) {
        const int b  = s * 8 + h * 32;   // tile-local batch base (8 batches)
        const int gb = b0 + b;           // global batch base
        unsigned hiA = 0, hiB = 0, lo4 = 0, cr = 0;
#pragma unroll
        for (int j = 0; j < 8; j++) {
            const float f = __expf(tile[c][b + j]);
            // fp16 bits rounded at bit 2 (round-half-up) -> m8 precision
            const unsigned hb =
                (unsigned)__half_as_ushort(__float2half_rn(f)) + 2u;
            const unsigned hby = (hb >> 8) & 0xFFu;
            if (j < 4) hiA |= hby << (8 * j);
            else       hiB |= hby << (8 * (j - 4));
            lo4 |= ((hb >> 4) & 0xFu) << (4 * j);
            cr  |= ((hb >> 2) & 0x3u) << (2 * j);
        }
        __stcg(reinterpret_cast<uint2*>(row + gb), make_uint2(hiA, hiB));
        __stcg(reinterpret_cast<unsigned*>(row + 128 + gb / 2), lo4);
        __stcg(reinterpret_cast<unsigned short*>(row + 192 + gb / 4),
               (unsigned short)cr);
    }
}

// ---------------------------------------------------------------------------
// Kernel 2: fused gather-reduce on 14-bit E. One warp per node; 8 nodes per
// 256-thr block; grid=512, bounds(256,4) => single wave (proven in R4).
// Lanes 0-15 even edges / 16-31 odd; per edge-lane: 3 loads (8B+4B+2B = 14B
// for 8 batches), reconstruct 4 half2, fp32 FMA accumulate.
// ---------------------------------------------------------------------------
__global__ void __launch_bounds__(256, 4) sum_nodes_kernel(
    const float* __restrict__ log_w, const int* __restrict__ cols,
    float* __restrict__ out) {
    const int tid   = threadIdx.x;
    const int wid   = tid >> 5;            // node-in-block 0..7
    const int lane  = tid & 31;
    const int node0 = blockIdx.x * 8;
    const int node  = node0 + wid;
    const int base  = node * DEGREE;

    __shared__ uint2 s_wo[8][64];          // .x = fp32 w bits, .y = c*224
    __shared__ float s_o[128][9];          // [batch][node-in-block], padded

    // Fused weight normalization: warp shuffle reduction over 64 edges.
    const float w0 = __expf(log_w[base + lane]);
    const float w1 = __expf(log_w[base + 32 + lane]);
    float ssum = w0 + w1;
#pragma unroll
    for (int o = 16; o; o >>= 1) ssum += __shfl_xor_sync(0xffffffffu, ssum, o);
    const float inv = 1.0f / ssum;
    {
        const float a = w0 * inv, b = w1 * inv;
        s_wo[wid][lane] =
            make_uint2(__float_as_uint(a), (unsigned)cols[base + lane] * ROWB);
        s_wo[wid][lane + 32] =
            make_uint2(__float_as_uint(b),
                       (unsigned)cols[base + 32 + lane] * ROWB);
    }
    __syncwarp();

    const int g    = lane & 15;            // batch-group: batches g*8..g*8+7
    const int side = lane >> 4;            // 0: even edges, 1: odd edges
    const int g8 = g * 8, g4 = g * 4, g2 = g * 2;
    const unsigned char* E = g_E14;

    float a0 = 0.f, a1 = 0.f, a2 = 0.f, a3 = 0.f;
    float a4 = 0.f, a5 = 0.f, a6 = 0.f, a7 = 0.f;

#pragma unroll 8
    for (int j = 0; j < 32; j++) {
        const uint2 wo = s_wo[wid][2 * j + side];
        const float w  = __uint_as_float(wo.x);
        const unsigned char* row = E + wo.y;
        const uint2    ph = __ldcg(reinterpret_cast<const uint2*>(row + g8));
        const unsigned q4 = __ldcg(reinterpret_cast<const unsigned*>(row + 128 + g4));
        const unsigned q2 = (unsigned)__ldcg(
            reinterpret_cast<const unsigned short*>(row + 192 + g2));

        // Rebuild fp16 pairs: bits = hi<<8 | nib<<4 | crumb<<2.
        const unsigned q4b = q4 >> 8,  q2b = q2 >> 4;
        const unsigned q4c = q4 >> 16, q2c = q2 >> 8;
        const unsigned q4d = q4 >> 24, q2d = q2 >> 12;
        unsigned u0 = __byte_perm(ph.x, 0, 0x1404) |
                      ((q4  & 0xFu) << 4) | ((q4  & 0xF0u) << 16) |
                      ((q2  & 0x3u) << 2) | ((q2  & 0xCu)  << 16);
        unsigned u1 = __byte_perm(ph.x, 0, 0x3424) |
                      ((q4b & 0xFu) << 4) | ((q4b & 0xF0u) << 16) |
                      ((q2b & 0x3u) << 2) | ((q2b & 0xCu)  << 16);
        unsigned u2 = __byte_perm(ph.y, 0, 0x1404) |
                      ((q4c & 0xFu) << 4) | ((q4c & 0xF0u) << 16) |
                      ((q2c & 0x3u) << 2) | ((q2c & 0xCu)  << 16);
        unsigned u3 = __byte_perm(ph.y, 0, 0x3424) |
                      ((q4d & 0xFu) << 4) | ((q4d & 0xF0u) << 16) |
                      ((q2d & 0x3u) << 2) | ((q2d & 0xCu)  << 16);

        float2 f;
        f = __half22float2(*reinterpret_cast<const __half2*>(&u0));
        a0 = fmaf(w, f.x, a0); a1 = fmaf(w, f.y, a1);
        f = __half22float2(*reinterpret_cast<const __half2*>(&u1));
        a2 = fmaf(w, f.x, a2); a3 = fmaf(w, f.y, a3);
        f = __half22float2(*reinterpret_cast<const __half2*>(&u2));
        a4 = fmaf(w, f.x, a4); a5 = fmaf(w, f.y, a5);
        f = __half22float2(*reinterpret_cast<const __half2*>(&u3));
        a6 = fmaf(w, f.x, a6); a7 = fmaf(w, f.y, a7);
    }

    // Merge even/odd sides within the warp; side-0 lanes finish with log.
    a0 += __shfl_xor_sync(0xffffffffu, a0, 16);
    a1 += __shfl_xor_sync(0xffffffffu, a1, 16);
    a2 += __shfl_xor_sync(0xffffffffu, a2, 16);
    a3 += __shfl_xor_sync(0xffffffffu, a3, 16);
    a4 += __shfl_xor_sync(0xffffffffu, a4, 16);
    a5 += __shfl_xor_sync(0xffffffffu, a5, 16);
    a6 += __shfl_xor_sync(0xffffffffu, a6, 16);
    a7 += __shfl_xor_sync(0xffffffffu, a7, 16);
    if (side == 0) {
        s_o[g8 + 0][wid] = __logf(a0);
        s_o[g8 + 1][wid] = __logf(a1);
        s_o[g8 + 2][wid] = __logf(a2);
        s_o[g8 + 3][wid] = __logf(a3);
        s_o[g8 + 4][wid] = __logf(a4);
        s_o[g8 + 5][wid] = __logf(a5);
        s_o[g8 + 6][wid] = __logf(a6);
        s_o[g8 + 7][wid] = __logf(a7);
    }
    __syncthreads();

    // Coalesced output: 8 adjacent nodes -> full 32B sectors.
    const int bb = tid >> 1;
    const int h  = (tid & 1) * 4;
    const float4 v = make_float4(s_o[bb][h + 0], s_o[bb][h + 1],
                                 s_o[bb][h + 2], s_o[bb][h + 3]);
    *reinterpret_cast<float4*>(&out[(size_t)bb * N_NODES + node0 + h]) = v;
}

// ---------------------------------------------------------------------------
extern "C" void kernel_launch(void* const* d_in, const int* in_sizes, int n_in,
                              void* d_out, int out_size) {
    const float* child_ll = (const float*)d_in[0];  // [128, 16384] f32
    const float* log_w    = (const float*)d_in[1];  // [262144] f32
    // d_in[2] = rows: structurally repeat(arange(4096), 64) — unused
    const int*   cols     = (const int*)d_in[3];    // [262144] i32
    float*       out      = (float*)d_out;          // [128, 4096] f32

    dim3 tg(N_CHILD / 64, BATCH / 64);              // (256, 2)
    exp_tr_kernel<<<tg, 256>>>(child_ll);
    sum_nodes_kernel<<<N_NODES / 8, 256>>>(log_w, cols, out);
}

// round 8
// speedup vs baseline: 1.2564x; 1.2564x over previous
#include <cuda_runtime.h>
#include <cuda_fp16.h>

#define N_NODES 4096
#define N_CHILD 16384
#define DEGREE  64
#define BATCH   128
#define NNZ     (N_NODES * DEGREE)

// Scratch: E_T[c][b] = exp(child_ll[b][c]) in fp16 (4 MB, L2-resident)
__device__ __align__(256) __half g_Eh[(size_t)N_CHILD * BATCH];

// ---------------------------------------------------------------------------
// Kernel 1: exp + transpose + fp16 convert.
// child_ll [B=128, C=16384] f32 row-major  ->  g_Eh [C, B] fp16.
// Two-phase: all 4 float4 loads issued before any smem store (MLP=4).
// ---------------------------------------------------------------------------
__global__ void __launch_bounds__(256) exp_tr_kernel(
    const float* __restrict__ child_ll) {
    __shared__ float tile[64][65];
    const int c0 = blockIdx.x * 64;
    const int b0 = blockIdx.y * 64;

    const int q  = threadIdx.x & 15;   // float4 index along c
    const int r0 = threadIdx.x >> 4;   // row (b) 0..15

    float4 v[4];
#pragma unroll
    for (int i = 0; i < 4; i++)
        v[i] = __ldcg(reinterpret_cast<const float4*>(
            &child_ll[(size_t)(b0 + r0 + i * 16) * N_CHILD + c0 + q * 4]));
#pragma unroll
    for (int i = 0; i < 4; i++) {
        const int r = r0 + i * 16;
        tile[q * 4 + 0][r] = v[i].x;
        tile[q * 4 + 1][r] = v[i].y;
        tile[q * 4 + 2][r] = v[i].z;
        tile[q * 4 + 3][r] = v[i].w;
    }
    __syncthreads();

    const int c = threadIdx.x >> 2;    // 0..63
    const int s = threadIdx.x & 3;     // 0..3
#pragma unroll
    for (int h = 0; h < 2; h++) {
        const int b = s * 8 + h * 32;
        __half2 hv[4];
#pragma unroll
        for (int j = 0; j < 4; j++) {
            const float f0 = __expf(tile[c][b + 2 * j]);
            const float f1 = __expf(tile[c][b + 2 * j + 1]);
            hv[j] = __floats2half2_rn(f0, f1);
        }
        __stcg(reinterpret_cast<uint4*>(&g_Eh[(size_t)(c0 + c) * BATCH + b0 + b]),
               *reinterpret_cast<const uint4*>(hv));
    }
}

// ---------------------------------------------------------------------------
// Kernel 2: fused gather-reduce (R5 structure, proven fastest).
// 2 warps per node, 4 nodes per 256-thr block, grid=1024, bounds(256,7):
// single wave. Gather via __ldg (L1 read-only cache: ~5% repeat hits save
// LTS bytes). Weight/col loads deduped to the half-0 warp only.
// ---------------------------------------------------------------------------
__global__ void __launch_bounds__(256, 7) sum_nodes_kernel(
    const float* __restrict__ log_w, const int* __restrict__ cols,
    float* __restrict__ out) {
    const int tid   = threadIdx.x;
    const int wid   = tid >> 5;            // 0..7
    const int lane  = tid & 31;
    const int nib   = wid >> 1;            // node-in-block 0..3
    const int half  = wid & 1;             // edge half: [half*32, half*32+32)
    const int node0 = blockIdx.x * 4;
    const int node  = node0 + nib;
    const int base  = node * DEGREE;

    __shared__ uint2 s_wo[4][64];          // .x = half2(w,w) bits, .y = c*128
    __shared__ float s_p[4][128];          // partials from half-0 warps
    __shared__ float s_o[128][5];          // [batch][node-in-block], padded

    // Weight normalization: only the half-0 warp of each pair (dedup LTS).
    if (half == 0) {
        const float w0 = __expf(__ldg(&log_w[base + lane]));
        const float w1 = __expf(__ldg(&log_w[base + 32 + lane]));
        float ssum = w0 + w1;
#pragma unroll
        for (int o = 16; o; o >>= 1)
            ssum += __shfl_xor_sync(0xffffffffu, ssum, o);
        const float inv = 1.0f / ssum;
        __half2 a = __float2half2_rn(w0 * inv);
        __half2 b = __float2half2_rn(w1 * inv);
        s_wo[nib][lane] = make_uint2(*reinterpret_cast<unsigned*>(&a),
                                     (unsigned)__ldg(&cols[base + lane]) * BATCH);
        s_wo[nib][lane + 32] =
            make_uint2(*reinterpret_cast<unsigned*>(&b),
                       (unsigned)__ldg(&cols[base + 32 + lane]) * BATCH);
    }
    __syncthreads();

    const int g    = lane & 15;            // batch-group: batches g*8..g*8+7
    const int side = lane >> 4;            // 0: even local edges, 1: odd
    const __half* Eg = g_Eh + g * 8;

    float fa[8] = {0.f, 0.f, 0.f, 0.f, 0.f, 0.f, 0.f, 0.f};

#pragma unroll
    for (int jj = 0; jj < 2; jj++) {
        __half2 hacc[4];
#pragma unroll
        for (int k = 0; k < 4; k++) hacc[k] = __float2half2_rn(0.f);
#pragma unroll
        for (int j8 = 0; j8 < 8; j8++) {
            const int e = half * 32 + (jj * 8 + j8) * 2 + side;
            const uint2 wo = s_wo[nib][e];
            const __half2 w2 = *reinterpret_cast<const __half2*>(&wo.x);
            const uint4 p = __ldg(reinterpret_cast<const uint4*>(Eg + wo.y));
            hacc[0] = __hfma2(w2, *reinterpret_cast<const __half2*>(&p.x), hacc[0]);
            hacc[1] = __hfma2(w2, *reinterpret_cast<const __half2*>(&p.y), hacc[1]);
            hacc[2] = __hfma2(w2, *reinterpret_cast<const __half2*>(&p.z), hacc[2]);
            hacc[3] = __hfma2(w2, *reinterpret_cast<const __half2*>(&p.w), hacc[3]);
        }
#pragma unroll
        for (int k = 0; k < 4; k++) {
            const float2 f = __half22float2(hacc[k]);
            fa[2 * k]     += f.x;
            fa[2 * k + 1] += f.y;
        }
    }

    // Merge even/odd sides within the warp.
#pragma unroll
    for (int k = 0; k < 8; k++)
        fa[k] += __shfl_xor_sync(0xffffffffu, fa[k], 16);

    // Merge the warp pair via smem; half-1 warp finishes with log.
    if (half == 0 && side == 0) {
#pragma unroll
        for (int k = 0; k < 8; k++) s_p[nib][g * 8 + k] = fa[k];
    }
    __syncthreads();
    if (half == 1 && side == 0) {
#pragma unroll
        for (int k = 0; k < 8; k++)
            s_o[g * 8 + k][nib] = __logf(s_p[nib][g * 8 + k] + fa[k]);
    }
    __syncthreads();

    // Coalesced output: thread b writes float4 -> out[b][node0..node0+3].
    if (tid < 128) {
        const float4 v = make_float4(s_o[tid][0], s_o[tid][1],
                                     s_o[tid][2], s_o[tid][3]);
        *reinterpret_cast<float4*>(&out[(size_t)tid * N_NODES + node0]) = v;
    }
}

// ---------------------------------------------------------------------------
extern "C" void kernel_launch(void* const* d_in, const int* in_sizes, int n_in,
                              void* d_out, int out_size) {
    const float* child_ll = (const float*)d_in[0];  // [128, 16384] f32
    const float* log_w    = (const float*)d_in[1];  // [262144] f32
    // d_in[2] = rows: structurally repeat(arange(4096), 64) — unused
    const int*   cols     = (const int*)d_in[3];    // [262144] i32
    float*       out      = (float*)d_out;          // [128, 4096] f32

    dim3 tg(N_CHILD / 64, BATCH / 64);              // (256, 2)
    exp_tr_kernel<<<tg, 256>>>(child_ll);
    sum_nodes_kernel<<<N_NODES / 4, 256>>>(log_w, cols, out);
}

// round 9
// speedup vs baseline: 1.3119x; 1.0442x over previous
#include <cuda_runtime.h>
#include <cuda_fp16.h>

#define N_NODES 4096
#define N_CHILD 16384
#define DEGREE  64
#define BATCH   128
#define NNZ     (N_NODES * DEGREE)

// Scratch: E_T[c][b] = exp(child_ll[b][c]) in fp16 (4 MB, L2-resident)
__device__ __align__(256) __half g_Eh[(size_t)N_CHILD * BATCH];

// ---------------------------------------------------------------------------
// Kernel 1: exp + transpose + fp16 convert (exact R5 version, proven fast).
// child_ll [B=128, C=16384] f32 row-major  ->  g_Eh [C, B] fp16.
// ---------------------------------------------------------------------------
__global__ void __launch_bounds__(256) exp_tr_kernel(
    const float* __restrict__ child_ll) {
    __shared__ float tile[64][65];
    const int c0 = blockIdx.x * 64;
    const int b0 = blockIdx.y * 64;

    const int q  = threadIdx.x & 15;   // float4 index along c
    const int r0 = threadIdx.x >> 4;   // row (b) 0..15
#pragma unroll
    for (int rr = 0; rr < 64; rr += 16) {
        const int r = r0 + rr;
        const float4 v = __ldcg(reinterpret_cast<const float4*>(
            &child_ll[(size_t)(b0 + r) * N_CHILD + c0 + q * 4]));
        tile[q * 4 + 0][r] = v.x;
        tile[q * 4 + 1][r] = v.y;
        tile[q * 4 + 2][r] = v.z;
        tile[q * 4 + 3][r] = v.w;
    }
    __syncthreads();

    const int c = threadIdx.x >> 2;    // 0..63
    const int s = threadIdx.x & 3;     // 0..3
#pragma unroll
    for (int h = 0; h < 2; h++) {
        const int b = s * 8 + h * 32;
        __half2 hv[4];
#pragma unroll
        for (int j = 0; j < 4; j++) {
            const float f0 = __expf(tile[c][b + 2 * j]);
            const float f1 = __expf(tile[c][b + 2 * j + 1]);
            hv[j] = __floats2half2_rn(f0, f1);
        }
        __stcg(reinterpret_cast<uint4*>(&g_Eh[(size_t)(c0 + c) * BATCH + b0 + b]),
               *reinterpret_cast<const uint4*>(hv));
    }
}

// ---------------------------------------------------------------------------
// Kernel 2: fused gather-reduce (R5 structure = fastest measured), with ONE
// change: log_w/cols loads deduped to the half-0 warp of each node pair
// (saves 2MB = ~0.1M LTS sectors vs R5). Gathers stay __ldcg (L2 path; R8
// proved __ldg/L1 regresses). 2 warps/node, grid=1024, bounds(256,7):
// single wave.
// ---------------------------------------------------------------------------
__global__ void __launch_bounds__(256, 7) sum_nodes_kernel(
    const float* __restrict__ log_w, const int* __restrict__ cols,
    float* __restrict__ out) {
    const int tid   = threadIdx.x;
    const int wid   = tid >> 5;            // 0..7
    const int lane  = tid & 31;
    const int nib   = wid >> 1;            // node-in-block 0..3
    const int half  = wid & 1;             // edge half: [half*32, half*32+32)
    const int node0 = blockIdx.x * 4;
    const int node  = node0 + nib;
    const int base  = node * DEGREE;

    __shared__ uint2 s_wo[4][64];          // .x = half2(w,w) bits, .y = c*128
    __shared__ float s_p[4][128];          // partials from half-0 warps
    __shared__ float s_o[128][5];          // [batch][node-in-block], padded

    // Fused weight normalization — half-0 warp only (dedup LTS reads).
    if (half == 0) {
        const float w0 = __expf(log_w[base + lane]);
        const float w1 = __expf(log_w[base + 32 + lane]);
        float ssum = w0 + w1;
#pragma unroll
        for (int o = 16; o; o >>= 1)
            ssum += __shfl_xor_sync(0xffffffffu, ssum, o);
        const float inv = 1.0f / ssum;
        __half2 a = __float2half2_rn(w0 * inv);
        __half2 b = __float2half2_rn(w1 * inv);
        s_wo[nib][lane] =
            make_uint2(*reinterpret_cast<unsigned*>(&a),
                       (unsigned)cols[base + lane] * BATCH);
        s_wo[nib][lane + 32] =
            make_uint2(*reinterpret_cast<unsigned*>(&b),
                       (unsigned)cols[base + 32 + lane] * BATCH);
    }
    __syncthreads();

    const int g    = lane & 15;            // batch-group: batches g*8..g*8+7
    const int side = lane >> 4;            // 0: even local edges, 1: odd
    const __half* Eg = g_Eh + g * 8;

    float fa[8] = {0.f, 0.f, 0.f, 0.f, 0.f, 0.f, 0.f, 0.f};

#pragma unroll
    for (int jj = 0; jj < 2; jj++) {
        __half2 hacc[4];
#pragma unroll
        for (int k = 0; k < 4; k++) hacc[k] = __float2half2_rn(0.f);
#pragma unroll
        for (int j8 = 0; j8 < 8; j8++) {
            const int e = half * 32 + (jj * 8 + j8) * 2 + side;
            const uint2 wo = s_wo[nib][e];
            const __half2 w2 = *reinterpret_cast<const __half2*>(&wo.x);
            const uint4 p = __ldcg(reinterpret_cast<const uint4*>(Eg + wo.y));
            hacc[0] = __hfma2(w2, *reinterpret_cast<const __half2*>(&p.x), hacc[0]);
            hacc[1] = __hfma2(w2, *reinterpret_cast<const __half2*>(&p.y), hacc[1]);
            hacc[2] = __hfma2(w2, *reinterpret_cast<const __half2*>(&p.z), hacc[2]);
            hacc[3] = __hfma2(w2, *reinterpret_cast<const __half2*>(&p.w), hacc[3]);
        }
#pragma unroll
        for (int k = 0; k < 4; k++) {
            const float2 f = __half22float2(hacc[k]);
            fa[2 * k]     += f.x;
            fa[2 * k + 1] += f.y;
        }
    }

    // Merge even/odd sides within the warp.
#pragma unroll
    for (int k = 0; k < 8; k++)
        fa[k] += __shfl_xor_sync(0xffffffffu, fa[k], 16);

    // Merge the warp pair via smem; half-1 warp finishes with log.
    if (half == 0 && side == 0) {
#pragma unroll
        for (int k = 0; k < 8; k++) s_p[nib][g * 8 + k] = fa[k];
    }
    __syncthreads();
    if (half == 1 && side == 0) {
#pragma unroll
        for (int k = 0; k < 8; k++)
            s_o[g * 8 + k][nib] = __logf(s_p[nib][g * 8 + k] + fa[k]);
    }
    __syncthreads();

    // Coalesced output: thread b writes float4 -> out[b][node0..node0+3].
    if (tid < 128) {
        const float4 v = make_float4(s_o[tid][0], s_o[tid][1],
                                     s_o[tid][2], s_o[tid][3]);
        *reinterpret_cast<float4*>(&out[(size_t)tid * N_NODES + node0]) = v;
    }
}

// ---------------------------------------------------------------------------
extern "C" void kernel_launch(void* const* d_in, const int* in_sizes, int n_in,
                              void* d_out, int out_size) {
    const float* child_ll = (const float*)d_in[0];  // [128, 16384] f32
    const float* log_w    = (const float*)d_in[1];  // [262144] f32
    // d_in[2] = rows: structurally repeat(arange(4096), 64) — unused
    const int*   cols     = (const int*)d_in[3];    // [262144] i32
    float*       out      = (float*)d_out;          // [128, 4096] f32

    dim3 tg(N_CHILD / 64, BATCH / 64);              // (256, 2)
    exp_tr_kernel<<<tg, 256>>>(child_ll);
    sum_nodes_kernel<<<N_NODES / 4, 256>>>(log_w, cols, out);
}